// round 1
// baseline (speedup 1.0000x reference)
#include <cuda_runtime.h>

// Problem constants
#define BB   64
#define SD   14
#define NS   196          // S*S
#define CC   32
#define OO   10
#define HH   16
#define EPSV 1e-9f
#define LOG2E 1.4426950408889634f
#define SCHUNK 28         // spatial positions per block
#define NBLK_S 7          // 196 / 28

#define BO (BB*OO)        // 640
#define ACC_STRIDE 33     // s0, s1[16], s2[16]

// Scratch: stats accumulators for the 3 passes + softmax params for 2 updates
__device__ float g_acc[3][BO*ACC_STRIDE];
__device__ float g_par[2][BO*ACC_STRIDE];

__global__ void zero_kernel() {
    int i = blockIdx.x * blockDim.x + threadIdx.x;
    if (i < 3 * BO * ACC_STRIDE) ((float*)g_acc)[i] = 0.0f;
}

// One sweep over all capsules.
// FUSED=false: iteration-0 accumulation with uniform rr = 1/O.
// FUSED=true : rr-update (softmax of log_ap) fused with next iteration's stats.
// Thread layout: t = c*10 + o  (c = channel 0..31 fixed per thread, o = 0..9).
// Block = (b, spatial chunk of 28). w[c,o] and per-(b,o) softmax params in registers.
template<bool FUSED>
__global__ __launch_bounds__(320)
void pass_kernel(const float* __restrict__ pose,
                 const float* __restrict__ act,
                 const float* __restrict__ w,
                 int par_idx, int acc_idx)
{
    const int t = threadIdx.x;
    const int o = t % OO;
    const int c = t / OO;
    const int b = blockIdx.y;
    const int sbase = blockIdx.x * SCHUNK;

    // w[c][o][j][k] -> 16 registers
    float wr[16];
    #pragma unroll
    for (int j = 0; j < 16; j++) wr[j] = w[(c * OO + o) * 16 + j];

    // per-(b,o) softmax params (pre-scaled by log2e)
    float c1 = 0.0f, Sh[16], MSh[16];
    if (FUSED) {
        const float* pp = &g_par[par_idx][(b * OO + o) * ACC_STRIDE];
        c1 = pp[0];
        #pragma unroll
        for (int h = 0; h < 16; h++) { Sh[h] = pp[1 + h]; MSh[h] = pp[17 + h]; }
    }

    // register accumulators
    float a0 = 0.0f, a1[16], a2[16];
    #pragma unroll
    for (int h = 0; h < 16; h++) { a1[h] = 0.0f; a2[h] = 0.0f; }

    __shared__ float lap_sm[320];
    __shared__ float e_sm[320];

    for (int si = 0; si < SCHUNK; si++) {
        const int s = sbase + si;
        const int cap = (b * NS + s) * CC + c;

        // votes: v[i*4+k] = sum_j pose[i*4+j] * w[j*4+k]
        const float4* p4 = reinterpret_cast<const float4*>(pose) + cap * 4;
        float v[16];
        #pragma unroll
        for (int i = 0; i < 4; i++) {
            float4 p = p4[i];
            #pragma unroll
            for (int k = 0; k < 4; k++) {
                float vv = p.x * wr[k];
                vv = fmaf(p.y, wr[4 + k], vv);
                vv = fmaf(p.z, wr[8 + k], vv);
                vv = fmaf(p.w, wr[12 + k], vv);
                v[i * 4 + k] = vv;
            }
        }
        // coordinate addition: h=0 gets row coord, h=1 gets col coord
        const int s1 = s / SD, s2 = s - s1 * SD;
        v[0] += (s1 + 0.5f) * (1.0f / SD);
        v[1] += (s2 + 0.5f) * (1.0f / SD);

        const float a = act[cap];
        float r;
        if (!FUSED) {
            r = a * (1.0f / OO);
        } else {
            // log_ap (base-2 scaled): c1 - sum_h ((v-m)^2 * log2e / (2 var))
            float lap = c1;
            #pragma unroll
            for (int h = 0; h < 16; h++) {
                float d = fmaf(v[h], Sh[h], -MSh[h]);
                lap = fmaf(d, -d, lap);
            }
            lap_sm[t] = lap;
            __syncthreads();
            const float* lrow = &lap_sm[c * OO];
            float mx = lrow[0];
            #pragma unroll
            for (int oo = 1; oo < OO; oo++) mx = fmaxf(mx, lrow[oo]);
            float e = exp2f(lap - mx);
            e_sm[t] = e;
            __syncthreads();
            const float* erow = &e_sm[c * OO];
            float sum = erow[0];
            #pragma unroll
            for (int oo = 1; oo < OO; oo++) sum += erow[oo];
            // rr = e/sum ; r = rr * a
            r = e * __fdividef(a, sum);
        }

        a0 += r;
        #pragma unroll
        for (int h = 0; h < 16; h++) {
            float rv = r * v[h];
            a1[h] += rv;
            a2[h] = fmaf(rv, v[h], a2[h]);
        }
    }

    // flush accumulators
    float* dst = &g_acc[acc_idx][(b * OO + o) * ACC_STRIDE];
    atomicAdd(dst, a0);
    #pragma unroll
    for (int h = 0; h < 16; h++) {
        atomicAdd(dst + 1 + h, a1[h]);
        atomicAdd(dst + 17 + h, a2[h]);
    }
}

// Per-(b,o) M-step: mean/var/activation; emits either softmax params for the
// next sweep or the final outputs.
__global__ void m_kernel(const float* __restrict__ beta_a,
                         const float* __restrict__ beta_v,
                         float* __restrict__ out,
                         int acc_idx, int par_idx,
                         float inv_temp, int is_final)
{
    const int idx = threadIdx.x;
    if (idx >= BO) return;
    const int o = idx % OO;
    const float* sacc = &g_acc[acc_idx][idx * ACC_STRIDE];
    const float s0 = sacc[0];
    const float denom = 1.0f / (s0 + EPSV);

    float m[16], var[16];
    float sumlog = 0.0f;
    #pragma unroll
    for (int h = 0; h < 16; h++) {
        float s1 = sacc[1 + h];
        float s2 = sacc[17 + h];
        float mh = s1 * denom;                      // = S1/(S0+eps)
        float num = s2 - 2.0f * mh * s1 + mh * mh * s0;  // sum r(v-m)^2
        float vh = num * denom + EPSV;
        m[h] = mh;
        var[h] = vh;
        sumlog += logf(vh);
    }
    float cost = (16.0f * beta_v[o] + 0.5f * sumlog) * s0;
    float aj = 1.0f / (1.0f + expf(-inv_temp * (beta_a[o] - cost)));

    if (is_final) {
        #pragma unroll
        for (int h = 0; h < 16; h++) out[idx * 16 + h] = m[h];
        out[BO * 16 + idx] = aj;
    } else {
        float* pp = &g_par[par_idx][idx * ACC_STRIDE];
        float c1 = logf(aj + EPSV);
        #pragma unroll
        for (int h = 0; h < 16; h++) {
            c1 -= 0.5f * logf(6.283185307179586f * var[h]);
            float S = sqrtf(LOG2E / (2.0f * var[h]));
            pp[1 + h] = S;
            pp[17 + h] = m[h] * S;
        }
        pp[0] = c1 * LOG2E;
    }
}

extern "C" void kernel_launch(void* const* d_in, const int* in_sizes, int n_in,
                              void* d_out, int out_size)
{
    const float* pose = (const float*)d_in[0];
    const float* act  = (const float*)d_in[1];
    const float* w    = (const float*)d_in[2];
    const float* ba   = (const float*)d_in[3];
    const float* bv   = (const float*)d_in[4];
    float* out = (float*)d_out;

    const int nz = 3 * BO * ACC_STRIDE;
    zero_kernel<<<(nz + 255) / 256, 256>>>();

    dim3 grid(NBLK_S, BB);

    // inv_temp(it) = 0.01 * (1 - 0.95^(it+1))
    const float it0 = 0.01f * (1.0f - 0.95f);
    const float it1 = 0.01f * (1.0f - 0.95f * 0.95f);
    const float it2 = 0.01f * (1.0f - 0.95f * 0.95f * 0.95f);

    // iteration 0: uniform rr
    pass_kernel<false><<<grid, 320>>>(pose, act, w, 0, 0);
    m_kernel<<<1, BO>>>(ba, bv, out, 0, 0, it0, 0);
    // iteration 1: rr update (from it0 stats) fused with stats accumulation
    pass_kernel<true><<<grid, 320>>>(pose, act, w, 0, 1);
    m_kernel<<<1, BO>>>(ba, bv, out, 1, 1, it1, 0);
    // iteration 2: rr update fused with final stats accumulation
    pass_kernel<true><<<grid, 320>>>(pose, act, w, 1, 2);
    m_kernel<<<1, BO>>>(ba, bv, out, 2, 0, it2, 1);
}

// round 4
// speedup vs baseline: 1.3316x; 1.3316x over previous
#include <cuda_runtime.h>

// Problem constants
#define BB   64
#define SD   14
#define NS   196          // S*S
#define CC   32
#define OO   10
#define OPAD 16           // o padded to 16 lanes for warp-local softmax
#define HH   16
#define EPSV 1e-9f
#define LOG2E 1.4426950408889634f
#define SCHUNK 28         // spatial positions per block (= 2 rows of 14)
#define NBLK_S 7          // 196 / 28

#define BO (BB*OO)        // 640
#define ACC_STRIDE 33     // s0, s1[16], s2[16]

// Scratch: stats accumulators for the 3 passes + softmax params for 2 updates
__device__ float g_acc[3][BO*ACC_STRIDE];
__device__ float g_par[2][BO*ACC_STRIDE];

__global__ void zero_kernel() {
    int i = blockIdx.x * blockDim.x + threadIdx.x;
    if (i < 3 * BO * ACC_STRIDE) ((float*)g_acc)[i] = 0.0f;
}

// One sweep over all capsules.
// FUSED=false: iteration-0 accumulation with uniform rr = 1/O.
// FUSED=true : rr-update (softmax of log_ap) fused with next iteration's stats.
//
// Thread layout: t = c_local*16 + o, o in [0,16) (lanes 0-15 / 16-31 of a warp
// form two softmax groups). Block = 256 threads = 16 channels x 16 o-slots.
// Grid: (s-chunk, c-half, b). Softmax is warp-local via shfl.bfly -> no
// __syncthreads in the main loop, no shared traffic for the softmax.
template<bool FUSED>
__global__ __launch_bounds__(256, 2)
void pass_kernel(const float* __restrict__ pose,
                 const float* __restrict__ act,
                 const float* __restrict__ w,
                 int par_idx, int acc_idx)
{
    const int t = threadIdx.x;
    const int o = t & (OPAD - 1);
    const int c = blockIdx.y * 16 + (t >> 4);
    const int b = blockIdx.z;
    const int sbase = blockIdx.x * SCHUNK;
    const bool live = (o < OO);

    // w[c][o][j][k] -> 16 registers (zeros for dummy o-slots)
    float wr[16];
    #pragma unroll
    for (int j = 0; j < 16; j++)
        wr[j] = live ? w[(c * OO + o) * 16 + j] : 0.0f;

    // per-(b,o) softmax params in shared, laid out [h][o] (broadcast across
    // the 16 c-groups, conflict-free: lanes 0-15 hit banks 0-15, lanes 16-31
    // hit the same addresses -> broadcast).
    __shared__ float sm_Sh[HH][OPAD];
    __shared__ float sm_MSh[HH][OPAD];
    __shared__ float sm_c1[OPAD];
    float c1r = 0.0f;
    if (FUSED) {
        if (t < OPAD) sm_c1[t] = -1e30f;
        if (t < HH * OPAD) { sm_Sh[t >> 4][t & 15] = 0.0f; sm_MSh[t >> 4][t & 15] = 0.0f; }
        __syncthreads();
        // load the 10*33 real params
        for (int i = t; i < OO * ACC_STRIDE; i += 256) {
            int oo = i / ACC_STRIDE, j = i - oo * ACC_STRIDE;
            float val = g_par[par_idx][(b * OO + oo) * ACC_STRIDE + j];
            if (j == 0)       sm_c1[oo] = val;
            else if (j < 17)  sm_Sh[j - 1][oo] = val;
            else              sm_MSh[j - 17][oo] = val;
        }
        __syncthreads();
        c1r = sm_c1[o];
    }

    // register accumulators
    float a0 = 0.0f, a1[16], a2[16];
    #pragma unroll
    for (int h = 0; h < 16; h++) { a1[h] = 0.0f; a2[h] = 0.0f; }

    // incremental spatial coordinates (avoid per-iter integer divide):
    // sbase is a multiple of 28 = 2 rows of 14, so rows start aligned.
    int sr = sbase / SD, sc = 0;
    float coord_r = (sr + 0.5f) * (1.0f / SD);
    float coord_c = 0.5f * (1.0f / SD);

    for (int si = 0; si < SCHUNK; si++) {
        const int s = sbase + si;
        const int cap = (b * NS + s) * CC + c;

        // votes: v[i*4+k] = sum_j pose[i*4+j] * w[j*4+k]
        const float4* p4 = reinterpret_cast<const float4*>(pose) + cap * 4;
        float v[16];
        #pragma unroll
        for (int i = 0; i < 4; i++) {
            float4 p = p4[i];
            #pragma unroll
            for (int k = 0; k < 4; k++) {
                float vv = p.x * wr[k];
                vv = fmaf(p.y, wr[4 + k], vv);
                vv = fmaf(p.z, wr[8 + k], vv);
                vv = fmaf(p.w, wr[12 + k], vv);
                v[i * 4 + k] = vv;
            }
        }
        // coordinate addition: h=0 gets row coord, h=1 gets col coord
        v[0] += coord_r;
        v[1] += coord_c;
        // advance coords
        sc++;
        coord_c += (1.0f / SD);
        if (sc == SD) { sc = 0; coord_c = 0.5f * (1.0f / SD); coord_r += (1.0f / SD); }

        const float a = act[cap];
        float r;
        if (!FUSED) {
            r = live ? a * (1.0f / OO) : 0.0f;
        } else {
            // log_ap (base-2 scaled): c1 - sum_h ((v-m)^2 * log2e / (2 var))
            // two partial accumulators halve the serial FMA chain
            float lapA = c1r, lapB = 0.0f;
            #pragma unroll
            for (int h = 0; h < 16; h += 2) {
                float dA = fmaf(v[h],     sm_Sh[h][o],     -sm_MSh[h][o]);
                float dB = fmaf(v[h + 1], sm_Sh[h + 1][o], -sm_MSh[h + 1][o]);
                lapA = fmaf(dA, -dA, lapA);
                lapB = fmaf(dB, -dB, lapB);
            }
            float lap = lapA + lapB;          // dummy lanes: -1e30
            // warp-local softmax over the 16-lane o-group
            float mx = lap;
            #pragma unroll
            for (int m = 8; m >= 1; m >>= 1)
                mx = fmaxf(mx, __shfl_xor_sync(0xFFFFFFFFu, mx, m));
            float e = exp2f(lap - mx);        // dummy lanes -> 0
            float sum = e;
            #pragma unroll
            for (int m = 8; m >= 1; m >>= 1)
                sum += __shfl_xor_sync(0xFFFFFFFFu, sum, m);
            r = e * __fdividef(a, sum);       // rr * a
        }

        a0 += r;
        #pragma unroll
        for (int h = 0; h < 16; h++) {
            float rv = r * v[h];
            a1[h] += rv;
            a2[h] = fmaf(rv, v[h], a2[h]);
        }
    }

    // lane-pair pre-reduction: lane o and lane o+16 of each warp target the
    // same (b,o) accumulator -> merge via shfl, halving global atomics.
    a0 += __shfl_down_sync(0xFFFFFFFFu, a0, 16);
    #pragma unroll
    for (int h = 0; h < 16; h++) {
        a1[h] += __shfl_down_sync(0xFFFFFFFFu, a1[h], 16);
        a2[h] += __shfl_down_sync(0xFFFFFFFFu, a2[h], 16);
    }

    // flush accumulators (lower half-warp, live o only)
    if ((t & 31) < OO) {
        float* dst = &g_acc[acc_idx][(b * OO + o) * ACC_STRIDE];
        atomicAdd(dst, a0);
        #pragma unroll
        for (int h = 0; h < 16; h++) {
            atomicAdd(dst + 1 + h, a1[h]);
            atomicAdd(dst + 17 + h, a2[h]);
        }
    }
}

// Per-(b,o) M-step: mean/var/activation; emits either softmax params for the
// next sweep or the final outputs.
__global__ void m_kernel(const float* __restrict__ beta_a,
                         const float* __restrict__ beta_v,
                         float* __restrict__ out,
                         int acc_idx, int par_idx,
                         float inv_temp, int is_final)
{
    const int idx = threadIdx.x;
    if (idx >= BO) return;
    const int o = idx % OO;
    const float* sacc = &g_acc[acc_idx][idx * ACC_STRIDE];
    const float s0 = sacc[0];
    const float denom = 1.0f / (s0 + EPSV);

    float m[16], var[16];
    float sumlog = 0.0f;
    #pragma unroll
    for (int h = 0; h < 16; h++) {
        float s1 = sacc[1 + h];
        float s2 = sacc[17 + h];
        float mh = s1 * denom;                           // = S1/(S0+eps)
        float num = s2 - 2.0f * mh * s1 + mh * mh * s0;  // sum r(v-m)^2
        float vh = num * denom + EPSV;
        m[h] = mh;
        var[h] = vh;
        sumlog += logf(vh);
    }
    float cost = (16.0f * beta_v[o] + 0.5f * sumlog) * s0;
    float aj = 1.0f / (1.0f + expf(-inv_temp * (beta_a[o] - cost)));

    if (is_final) {
        #pragma unroll
        for (int h = 0; h < 16; h++) out[idx * 16 + h] = m[h];
        out[BO * 16 + idx] = aj;
    } else {
        float* pp = &g_par[par_idx][idx * ACC_STRIDE];
        float c1 = logf(aj + EPSV);
        #pragma unroll
        for (int h = 0; h < 16; h++) {
            c1 -= 0.5f * logf(6.283185307179586f * var[h]);
            float S = sqrtf(LOG2E / (2.0f * var[h]));
            pp[1 + h] = S;
            pp[17 + h] = m[h] * S;
        }
        pp[0] = c1 * LOG2E;
    }
}

extern "C" void kernel_launch(void* const* d_in, const int* in_sizes, int n_in,
                              void* d_out, int out_size)
{
    const float* pose = (const float*)d_in[0];
    const float* act  = (const float*)d_in[1];
    const float* w    = (const float*)d_in[2];
    const float* ba   = (const float*)d_in[3];
    const float* bv   = (const float*)d_in[4];
    float* out = (float*)d_out;

    const int nz = 3 * BO * ACC_STRIDE;
    zero_kernel<<<(nz + 255) / 256, 256>>>();

    dim3 grid(NBLK_S, 2, BB);   // s-chunk, c-half, batch

    // inv_temp(it) = 0.01 * (1 - 0.95^(it+1))
    const float it0 = 0.01f * (1.0f - 0.95f);
    const float it1 = 0.01f * (1.0f - 0.95f * 0.95f);
    const float it2 = 0.01f * (1.0f - 0.95f * 0.95f * 0.95f);

    // iteration 0: uniform rr
    pass_kernel<false><<<grid, 256>>>(pose, act, w, 0, 0);
    m_kernel<<<1, BO>>>(ba, bv, out, 0, 0, it0, 0);
    // iteration 1: rr update (from it0 stats) fused with stats accumulation
    pass_kernel<true><<<grid, 256>>>(pose, act, w, 0, 1);
    m_kernel<<<1, BO>>>(ba, bv, out, 1, 1, it1, 0);
    // iteration 2: rr update fused with final stats accumulation
    pass_kernel<true><<<grid, 256>>>(pose, act, w, 1, 2);
    m_kernel<<<1, BO>>>(ba, bv, out, 2, 0, it2, 1);
}